// round 15
// baseline (speedup 1.0000x reference)
#include <cuda_runtime.h>
#include <cstdint>

// WaveNet dilated causal conv stack.
// 2-CTA cluster per batch element; fused conv+io; ping-pong h in SMEM.
// 2 positions/thread (float2), NTH=544 one-shot bodies.
// Register-tail halo pushes (R14). Single change vs R14: constant weights
// loaded as float2 pairs (io loop restructured ci-outer/co-inner).
// Split points: M0=1088; M_i = 1086 + 2^(i+1).

#define NTH 544
#define LBUF 2176
#define FRAME 128
#define TFULL 4096

typedef unsigned long long u64;

#define OC0   0
#define OCK   24      // [(i-1)*3+w][ci][co]
#define OCB   1752    // [i][co]
#define OIOK  1832    // [i][ci][co]
#define OIOB  2408    // [i][co]
#define OMIX  2480    // [i][co]
#define OMIXB 2560
#define NW    2561

__constant__ __align__(16) float Wc[NW + 3];
__device__ float Wstage[NW];

__device__ __forceinline__ float2 W2(int idx) { return *(const float2*)&Wc[idx]; }

__device__ __forceinline__ uint32_t s2u(const void* p) {
    return (uint32_t)__cvta_generic_to_shared(p);
}
__device__ __forceinline__ uint32_t mapa_peer(uint32_t a, uint32_t peer) {
    uint32_t r;
    asm volatile("mapa.shared::cluster.u32 %0, %1, %2;" : "=r"(r) : "r"(a), "r"(peer));
    return r;
}
__device__ __forceinline__ void st_dsm64(uint32_t a, float x, float y) {
    u64 v = (u64)__float_as_uint(x) | ((u64)__float_as_uint(y) << 32);
    asm volatile("st.shared::cluster.b64 [%0], %1;" :: "r"(a), "l"(v) : "memory");
}
#define CS() do { asm volatile("barrier.cluster.arrive.aligned;" ::: "memory"); \
                  asm volatile("barrier.cluster.wait.aligned;" ::: "memory"); } while(0)

__global__ void pack_weights(const float* __restrict__ c0,  const float* __restrict__ ck,
                             const float* __restrict__ cb,  const float* __restrict__ iok,
                             const float* __restrict__ iob, const float* __restrict__ mix,
                             const float* __restrict__ mixb) {
    int i = blockIdx.x * blockDim.x + threadIdx.x;
    if (i >= NW) return;
    float v;
    if      (i < OCK)   v = c0[i - OC0];
    else if (i < OCB)   v = ck[i - OCK];
    else if (i < OIOK)  v = cb[i - OCB];
    else if (i < OIOB)  v = iok[i - OIOK];
    else if (i < OMIX)  v = iob[i - OIOB];
    else if (i < OMIXB) v = mix[i - OMIX];
    else                v = mixb[0];
    Wstage[i] = v;
}

extern __shared__ float smem[];

__global__ __launch_bounds__(NTH) __cluster_dims__(2, 1, 1)
void wavenet_kernel(const float* __restrict__ X, float* __restrict__ out)
{
    float* xb   = smem;              // LBUF
    float* hA   = smem + LBUF;       // 8*LBUF   h[c*LBUF + l]
    float* hB   = smem + 9 * LBUF;   // 8*LBUF
    float* oacc = smem + 17 * LBUF;  // FRAME

    const int tid = threadIdx.x;
    uint32_t rank;
    asm("mov.u32 %0, %%cluster_ctarank;" : "=r"(rank));
    const uint32_t peer = rank ^ 1u;
    const int b = blockIdx.x >> 1;
    const float* x = X + b * TFULL + (TFULL - LBUF);

    for (int l = tid; l < LBUF; l += NTH) xb[l] = x[l];
    if (rank && tid < FRAME) oacc[tid] = Wc[OMIXB];
    __syncthreads();

    // ---- layer 0 (pairs) -> hA; producer pushes its boundary pair from regs ----
    {
        const int M = 1088;
        const int lo = rank ? M : 2;
        const int hi = rank ? LBUF : M;
        const uint32_t pb = mapa_peer(s2u(hA), peer);
        for (int l = lo + 2 * tid; l < hi; l += 2 * NTH) {
            float2 A = *(const float2*)&xb[l - 2];
            float2 B = *(const float2*)&xb[l];
            float acc0[8], acc1[8];
#pragma unroll
            for (int cp = 0; cp < 4; cp++) {
                float2 w0 = W2(OC0 + 2 * cp);
                float2 w1 = W2(OC0 + 8 + 2 * cp);
                float2 w2 = W2(OC0 + 16 + 2 * cp);
                float2 bb = W2(OCB + 2 * cp);
                acc0[2*cp]   = fmaxf(fmaf(B.x, w2.x, fmaf(A.y, w1.x, fmaf(A.x, w0.x, bb.x))), 0.0f);
                acc0[2*cp+1] = fmaxf(fmaf(B.x, w2.y, fmaf(A.y, w1.y, fmaf(A.x, w0.y, bb.y))), 0.0f);
                acc1[2*cp]   = fmaxf(fmaf(B.y, w2.x, fmaf(B.x, w1.x, fmaf(A.y, w0.x, bb.x))), 0.0f);
                acc1[2*cp+1] = fmaxf(fmaf(B.y, w2.y, fmaf(B.x, w1.y, fmaf(A.y, w0.y, bb.y))), 0.0f);
            }
            if (l >= LBUF - FRAME) {
                float m0 = 0.0f, m1 = 0.0f;
#pragma unroll
                for (int cp = 0; cp < 4; cp++) {
                    float2 mw = W2(OMIX + 2 * cp);
                    m0 = fmaf(acc0[2*cp], mw.x, fmaf(acc0[2*cp+1], mw.y, m0));
                    m1 = fmaf(acc1[2*cp], mw.x, fmaf(acc1[2*cp+1], mw.y, m1));
                }
                oacc[l - (LBUF - FRAME)]     += m0;
                oacc[l - (LBUF - FRAME) + 1] += m1;
            }
            float o0[8], o1[8];
#pragma unroll
            for (int cp = 0; cp < 4; cp++) {
                float2 bb = W2(OIOB + 2 * cp);
                o0[2*cp] = bb.x + B.x; o0[2*cp+1] = bb.y + B.x;
                o1[2*cp] = bb.x + B.y; o1[2*cp+1] = bb.y + B.y;
            }
#pragma unroll
            for (int ci = 0; ci < 8; ci++) {
#pragma unroll
                for (int cp = 0; cp < 4; cp++) {
                    float2 wk = W2(OIOK + ci * 8 + 2 * cp);
                    o0[2*cp]   = fmaf(acc0[ci], wk.x, o0[2*cp]);
                    o0[2*cp+1] = fmaf(acc0[ci], wk.y, o0[2*cp+1]);
                    o1[2*cp]   = fmaf(acc1[ci], wk.x, o1[2*cp]);
                    o1[2*cp+1] = fmaf(acc1[ci], wk.y, o1[2*cp+1]);
                }
            }
#pragma unroll
            for (int co = 0; co < 8; co++)
                *(float2*)(hA + co * LBUF + l) = make_float2(o0[co], o1[co]);
            if (l == (rank ? 1088 : 1086)) {
#pragma unroll
                for (int co = 0; co < 8; co++)
                    st_dsm64(pb + (uint32_t)(co * LBUF + l) * 4u, o0[co], o1[co]);
            }
        }
    }
    CS();

    // ---- layers 1..8 (pairs), ping-pong, register-tail push halos ----
#pragma unroll
    for (int i = 1; i < 9; i++) {
        const int d = 1 << i;
        const int S = (4 << i) - 2;            // 2*(2^{i+1}-1)
        const int M = 1086 + (2 << i);
        const int W = 2 << i;                  // halo width for layer i+1
        float* cur = (i & 1) ? hA : hB;
        float* nxt = (i & 1) ? hB : hA;
        const uint32_t pb = mapa_peer(s2u(nxt), peer);

        const int lo = rank ? M : S;
        const int hi = rank ? LBUF : M;
        for (int l = lo + 2 * tid; l < hi; l += 2 * NTH) {
            float acc0[8], acc1[8], hl0[8], hl1[8];
#pragma unroll
            for (int cp = 0; cp < 4; cp++) {
                float2 bb = W2(OCB + i * 8 + 2 * cp);
                acc0[2*cp] = bb.x; acc0[2*cp+1] = bb.y;
                acc1[2*cp] = bb.x; acc1[2*cp+1] = bb.y;
            }
#pragma unroll
            for (int w = 0; w < 3; w++) {
                const int off = (2 - w) * d;
#pragma unroll
                for (int ci = 0; ci < 8; ci++) {
                    float2 v = *(const float2*)(cur + ci * LBUF + (l - off));
                    if (w == 2) { hl0[ci] = v.x; hl1[ci] = v.y; }
#pragma unroll
                    for (int cp = 0; cp < 4; cp++) {
                        float2 wk = W2(OCK + (((i - 1) * 3 + w) * 8 + ci) * 8 + 2 * cp);
                        acc0[2*cp]   = fmaf(v.x, wk.x, acc0[2*cp]);
                        acc0[2*cp+1] = fmaf(v.x, wk.y, acc0[2*cp+1]);
                        acc1[2*cp]   = fmaf(v.y, wk.x, acc1[2*cp]);
                        acc1[2*cp+1] = fmaf(v.y, wk.y, acc1[2*cp+1]);
                    }
                }
            }
#pragma unroll
            for (int co = 0; co < 8; co++) { acc0[co] = fmaxf(acc0[co], 0.0f); acc1[co] = fmaxf(acc1[co], 0.0f); }
            if (l >= LBUF - FRAME) {
                float m0 = 0.0f, m1 = 0.0f;
#pragma unroll
                for (int cp = 0; cp < 4; cp++) {
                    float2 mw = W2(OMIX + i * 8 + 2 * cp);
                    m0 = fmaf(acc0[2*cp], mw.x, fmaf(acc0[2*cp+1], mw.y, m0));
                    m1 = fmaf(acc1[2*cp], mw.x, fmaf(acc1[2*cp+1], mw.y, m1));
                }
                oacc[l - (LBUF - FRAME)]     += m0;
                oacc[l - (LBUF - FRAME) + 1] += m1;
            }
            float o0[8], o1[8];
#pragma unroll
            for (int cp = 0; cp < 4; cp++) {
                float2 bb = W2(OIOB + i * 8 + 2 * cp);
                o0[2*cp] = bb.x + hl0[2*cp]; o0[2*cp+1] = bb.y + hl0[2*cp+1];
                o1[2*cp] = bb.x + hl1[2*cp]; o1[2*cp+1] = bb.y + hl1[2*cp+1];
            }
#pragma unroll
            for (int ci = 0; ci < 8; ci++) {
#pragma unroll
                for (int cp = 0; cp < 4; cp++) {
                    float2 wk = W2(OIOK + (i * 8 + ci) * 8 + 2 * cp);
                    o0[2*cp]   = fmaf(acc0[ci], wk.x, o0[2*cp]);
                    o0[2*cp+1] = fmaf(acc0[ci], wk.y, o0[2*cp+1]);
                    o1[2*cp]   = fmaf(acc1[ci], wk.x, o1[2*cp]);
                    o1[2*cp+1] = fmaf(acc1[ci], wk.y, o1[2*cp+1]);
                }
            }
#pragma unroll
            for (int co = 0; co < 8; co++)
                *(float2*)(nxt + co * LBUF + l) = make_float2(o0[co], o1[co]);
            bool push;
            if (i == 8)
                push = rank ? false : ((l >= 1024 && l < 1152) || (l >= 1536 && l < 1598));
            else
                push = rank ? (l >= M && l < M + W) : (l >= M - W && l < M);
            if (push) {
#pragma unroll
                for (int co = 0; co < 8; co++)
                    st_dsm64(pb + (uint32_t)(co * LBUF + l) * 4u, o0[co], o1[co]);
            }
        }
        CS();
    }

    // ---- layer 9 (rank1 only, pairs): reads own hA, last FRAME positions ----
    if (rank) {
        const int i = 9, d = 512;
        for (int l = (LBUF - FRAME) + 2 * tid; l < LBUF; l += 2 * NTH) {
            float acc0[8], acc1[8];
#pragma unroll
            for (int cp = 0; cp < 4; cp++) {
                float2 bb = W2(OCB + i * 8 + 2 * cp);
                acc0[2*cp] = bb.x; acc0[2*cp+1] = bb.y;
                acc1[2*cp] = bb.x; acc1[2*cp+1] = bb.y;
            }
#pragma unroll
            for (int w = 0; w < 3; w++) {
                const int off = (2 - w) * d;
#pragma unroll
                for (int ci = 0; ci < 8; ci++) {
                    float2 v = *(const float2*)(hA + ci * LBUF + (l - off));
#pragma unroll
                    for (int cp = 0; cp < 4; cp++) {
                        float2 wk = W2(OCK + (((i - 1) * 3 + w) * 8 + ci) * 8 + 2 * cp);
                        acc0[2*cp]   = fmaf(v.x, wk.x, acc0[2*cp]);
                        acc0[2*cp+1] = fmaf(v.x, wk.y, acc0[2*cp+1]);
                        acc1[2*cp]   = fmaf(v.y, wk.x, acc1[2*cp]);
                        acc1[2*cp+1] = fmaf(v.y, wk.y, acc1[2*cp+1]);
                    }
                }
            }
            float m0 = 0.0f, m1 = 0.0f;
#pragma unroll
            for (int cp = 0; cp < 4; cp++) {
                float2 mw = W2(OMIX + i * 8 + 2 * cp);
                m0 = fmaf(fmaxf(acc0[2*cp], 0.0f), mw.x, fmaf(fmaxf(acc0[2*cp+1], 0.0f), mw.y, m0));
                m1 = fmaf(fmaxf(acc1[2*cp], 0.0f), mw.x, fmaf(fmaxf(acc1[2*cp+1], 0.0f), mw.y, m1));
            }
            oacc[l - (LBUF - FRAME)]     += m0;
            oacc[l - (LBUF - FRAME) + 1] += m1;
        }
        __syncthreads();
        if (tid < FRAME) out[b * FRAME + tid] = oacc[tid];
    }
}

static const int SMEM_BYTES = (17 * LBUF + FRAME) * (int)sizeof(float);

extern "C" void kernel_launch(void* const* d_in, const int* in_sizes, int n_in,
                              void* d_out, int out_size) {
    (void)in_sizes; (void)n_in; (void)out_size;
    cudaFuncSetAttribute(wavenet_kernel, cudaFuncAttributeMaxDynamicSharedMemorySize, SMEM_BYTES);

    pack_weights<<<(NW + 511) / 512, 512>>>(
        (const float*)d_in[1], (const float*)d_in[2], (const float*)d_in[3],
        (const float*)d_in[4], (const float*)d_in[5], (const float*)d_in[6],
        (const float*)d_in[7]);

    void* wp = nullptr;
    cudaGetSymbolAddress(&wp, Wstage);
    cudaMemcpyToSymbolAsync(Wc, wp, NW * sizeof(float), 0, cudaMemcpyDeviceToDevice, 0);

    wavenet_kernel<<<128, NTH, SMEM_BYTES>>>((const float*)d_in[0], (float*)d_out);
}

// round 16
// speedup vs baseline: 1.0021x; 1.0021x over previous
#include <cuda_runtime.h>
#include <cstdint>

// WaveNet dilated causal conv stack.
// 2-CTA cluster per batch element; fused conv+io; ping-pong h in SMEM.
// 2 positions/thread (float2), NTH=544 one-shot bodies, scalar const weights.
// Register-tail halo pushes (R14). Single change vs R14: cluster barriers
// replaced by __syncthreads + 1-arrival mbarrier handshake (release/acquire
// cluster scope); one initial cluster.sync for barrier-init visibility.
// Split points: M0=1088; M_i = 1086 + 2^(i+1).

#define NTH 544
#define LBUF 2176
#define FRAME 128
#define TFULL 4096

typedef unsigned long long u64;

#define OC0   0
#define OCK   24      // [(i-1)*3+w][ci][co]
#define OCB   1752    // [i][co]
#define OIOK  1832    // [i][ci][co]
#define OIOB  2408    // [i][co]
#define OMIX  2480    // [i][co]
#define OMIXB 2560
#define NW    2561

__constant__ float Wc[NW];
__device__ float Wstage[NW];

__device__ __forceinline__ uint32_t s2u(const void* p) {
    return (uint32_t)__cvta_generic_to_shared(p);
}
__device__ __forceinline__ uint32_t mapa_peer(uint32_t a, uint32_t peer) {
    uint32_t r;
    asm volatile("mapa.shared::cluster.u32 %0, %1, %2;" : "=r"(r) : "r"(a), "r"(peer));
    return r;
}
__device__ __forceinline__ void st_dsm64(uint32_t a, float x, float y) {
    u64 v = (u64)__float_as_uint(x) | ((u64)__float_as_uint(y) << 32);
    asm volatile("st.shared::cluster.b64 [%0], %1;" :: "r"(a), "l"(v) : "memory");
}
#define CS() do { asm volatile("barrier.cluster.arrive.aligned;" ::: "memory"); \
                  asm volatile("barrier.cluster.wait.aligned;" ::: "memory"); } while(0)

__device__ __forceinline__ void mbar_init1(uint32_t bar) {
    asm volatile("mbarrier.init.shared.b64 [%0], 1;" :: "r"(bar) : "memory");
}
__device__ __forceinline__ void mbar_arrive_peer(uint32_t own_bar, uint32_t peer) {
    uint32_t r = mapa_peer(own_bar, peer);
    asm volatile("mbarrier.arrive.release.cluster.shared::cluster.b64 _, [%0];"
                 :: "r"(r) : "memory");
}
__device__ __forceinline__ void mbar_wait(uint32_t bar, uint32_t parity) {
    asm volatile(
        "{\n\t"
        ".reg .pred P;\n\t"
        "WL_%=:\n\t"
        "mbarrier.try_wait.parity.acquire.cluster.shared::cta.b64 P, [%0], %1, 0x989680;\n\t"
        "@!P bra WL_%=;\n\t"
        "}"
        :: "r"(bar), "r"(parity) : "memory");
}

__global__ void pack_weights(const float* __restrict__ c0,  const float* __restrict__ ck,
                             const float* __restrict__ cb,  const float* __restrict__ iok,
                             const float* __restrict__ iob, const float* __restrict__ mix,
                             const float* __restrict__ mixb) {
    int i = blockIdx.x * blockDim.x + threadIdx.x;
    if (i >= NW) return;
    float v;
    if      (i < OCK)   v = c0[i - OC0];
    else if (i < OCB)   v = ck[i - OCK];
    else if (i < OIOK)  v = cb[i - OCB];
    else if (i < OIOB)  v = iok[i - OIOK];
    else if (i < OMIX)  v = iob[i - OIOB];
    else if (i < OMIXB) v = mix[i - OMIX];
    else                v = mixb[0];
    Wstage[i] = v;
}

extern __shared__ float smem[];

__global__ __launch_bounds__(NTH) __cluster_dims__(2, 1, 1)
void wavenet_kernel(const float* __restrict__ X, float* __restrict__ out)
{
    float* xb   = smem;                    // LBUF
    float* hA   = smem + LBUF;             // 8*LBUF   h[c*LBUF + l]
    float* hB   = smem + 9 * LBUF;         // 8*LBUF
    float* oacc = smem + 17 * LBUF;        // FRAME
    const uint32_t bar = s2u(smem + 17 * LBUF + FRAME);  // 8-byte mbarrier

    const int tid = threadIdx.x;
    uint32_t rank;
    asm("mov.u32 %0, %%cluster_ctarank;" : "=r"(rank));
    const uint32_t peer = rank ^ 1u;
    const int b = blockIdx.x >> 1;
    const float* x = X + b * TFULL + (TFULL - LBUF);
    uint32_t ph = 0;

    if (tid == 0) mbar_init1(bar);
    for (int l = tid; l < LBUF; l += NTH) xb[l] = x[l];
    if (rank && tid < FRAME) oacc[tid] = Wc[OMIXB];
    __syncthreads();
    CS();   // both CTAs' mbarriers initialized before any arrive

    // ---- layer 0 (pairs) -> hA; producer pushes its boundary pair from regs ----
    {
        const int M = 1088;
        const int lo = rank ? M : 2;
        const int hi = rank ? LBUF : M;
        const uint32_t pb = mapa_peer(s2u(hA), peer);
        for (int l = lo + 2 * tid; l < hi; l += 2 * NTH) {
            float2 A = *(const float2*)&xb[l - 2];
            float2 B = *(const float2*)&xb[l];
            float acc0[8], acc1[8];
#pragma unroll
            for (int co = 0; co < 8; co++) {
                float w0 = Wc[OC0 + co], w1 = Wc[OC0 + 8 + co], w2 = Wc[OC0 + 16 + co];
                float bb = Wc[OCB + co];
                acc0[co] = fmaxf(fmaf(B.x, w2, fmaf(A.y, w1, fmaf(A.x, w0, bb))), 0.0f);
                acc1[co] = fmaxf(fmaf(B.y, w2, fmaf(B.x, w1, fmaf(A.y, w0, bb))), 0.0f);
            }
            if (l >= LBUF - FRAME) {
                float m0 = 0.0f, m1 = 0.0f;
#pragma unroll
                for (int co = 0; co < 8; co++) {
                    float mw = Wc[OMIX + co];
                    m0 = fmaf(acc0[co], mw, m0); m1 = fmaf(acc1[co], mw, m1);
                }
                oacc[l - (LBUF - FRAME)]     += m0;
                oacc[l - (LBUF - FRAME) + 1] += m1;
            }
            float o0[8], o1[8];
#pragma unroll
            for (int co = 0; co < 8; co++) {
                float bb = Wc[OIOB + co];
                float a0 = bb + B.x, a1 = bb + B.y;
#pragma unroll
                for (int ci = 0; ci < 8; ci++) {
                    float wk = Wc[OIOK + ci * 8 + co];
                    a0 = fmaf(acc0[ci], wk, a0); a1 = fmaf(acc1[ci], wk, a1);
                }
                o0[co] = a0; o1[co] = a1;
                *(float2*)(hA + co * LBUF + l) = make_float2(a0, a1);
            }
            if (l == (rank ? 1088 : 1086)) {
#pragma unroll
                for (int co = 0; co < 8; co++)
                    st_dsm64(pb + (uint32_t)(co * LBUF + l) * 4u, o0[co], o1[co]);
            }
        }
        __syncthreads();
        if (tid == 0) mbar_arrive_peer(bar, peer);
        mbar_wait(bar, ph); ph ^= 1;
    }

    // ---- layers 1..8 (pairs), ping-pong, register-tail push halos ----
#pragma unroll
    for (int i = 1; i < 9; i++) {
        const int d = 1 << i;
        const int S = (4 << i) - 2;            // 2*(2^{i+1}-1)
        const int M = 1086 + (2 << i);
        const int W = 2 << i;                  // halo width for layer i+1
        float* cur = (i & 1) ? hA : hB;
        float* nxt = (i & 1) ? hB : hA;
        const uint32_t pb = mapa_peer(s2u(nxt), peer);

        const int lo = rank ? M : S;
        const int hi = rank ? LBUF : M;
        for (int l = lo + 2 * tid; l < hi; l += 2 * NTH) {
            float acc0[8], acc1[8], hl0[8], hl1[8];
#pragma unroll
            for (int co = 0; co < 8; co++) { acc0[co] = Wc[OCB + i * 8 + co]; acc1[co] = acc0[co]; }
#pragma unroll
            for (int w = 0; w < 3; w++) {
                const int off = (2 - w) * d;
#pragma unroll
                for (int ci = 0; ci < 8; ci++) {
                    float2 v = *(const float2*)(cur + ci * LBUF + (l - off));
                    if (w == 2) { hl0[ci] = v.x; hl1[ci] = v.y; }
#pragma unroll
                    for (int co = 0; co < 8; co++) {
                        float wk = Wc[OCK + (((i - 1) * 3 + w) * 8 + ci) * 8 + co];
                        acc0[co] = fmaf(v.x, wk, acc0[co]); acc1[co] = fmaf(v.y, wk, acc1[co]);
                    }
                }
            }
#pragma unroll
            for (int co = 0; co < 8; co++) { acc0[co] = fmaxf(acc0[co], 0.0f); acc1[co] = fmaxf(acc1[co], 0.0f); }
            if (l >= LBUF - FRAME) {
                float m0 = 0.0f, m1 = 0.0f;
#pragma unroll
                for (int co = 0; co < 8; co++) {
                    float mw = Wc[OMIX + i * 8 + co];
                    m0 = fmaf(acc0[co], mw, m0); m1 = fmaf(acc1[co], mw, m1);
                }
                oacc[l - (LBUF - FRAME)]     += m0;
                oacc[l - (LBUF - FRAME) + 1] += m1;
            }
            float o0[8], o1[8];
#pragma unroll
            for (int co = 0; co < 8; co++) {
                float bb = Wc[OIOB + i * 8 + co];
                float a0 = bb + hl0[co], a1 = bb + hl1[co];
#pragma unroll
                for (int ci = 0; ci < 8; ci++) {
                    float wk = Wc[OIOK + (i * 8 + ci) * 8 + co];
                    a0 = fmaf(acc0[ci], wk, a0); a1 = fmaf(acc1[ci], wk, a1);
                }
                o0[co] = a0; o1[co] = a1;
                *(float2*)(nxt + co * LBUF + l) = make_float2(a0, a1);
            }
            bool push;
            if (i == 8)   // layer 9 runs on rank1 only; rank0 pushes its strips
                push = rank ? false : ((l >= 1024 && l < 1152) || (l >= 1536 && l < 1598));
            else
                push = rank ? (l >= M && l < M + W) : (l >= M - W && l < M);
            if (push) {
#pragma unroll
                for (int co = 0; co < 8; co++)
                    st_dsm64(pb + (uint32_t)(co * LBUF + l) * 4u, o0[co], o1[co]);
            }
        }
        __syncthreads();
        if (tid == 0) mbar_arrive_peer(bar, peer);
        mbar_wait(bar, ph); ph ^= 1;
    }

    // ---- layer 9 (rank1 only, pairs): reads own hA, last FRAME positions ----
    if (rank) {
        const int i = 9, d = 512;
        for (int l = (LBUF - FRAME) + 2 * tid; l < LBUF; l += 2 * NTH) {
            float acc0[8], acc1[8];
#pragma unroll
            for (int co = 0; co < 8; co++) { acc0[co] = Wc[OCB + i * 8 + co]; acc1[co] = acc0[co]; }
#pragma unroll
            for (int w = 0; w < 3; w++) {
                const int off = (2 - w) * d;
#pragma unroll
                for (int ci = 0; ci < 8; ci++) {
                    float2 v = *(const float2*)(hA + ci * LBUF + (l - off));
#pragma unroll
                    for (int co = 0; co < 8; co++) {
                        float wk = Wc[OCK + (((i - 1) * 3 + w) * 8 + ci) * 8 + co];
                        acc0[co] = fmaf(v.x, wk, acc0[co]); acc1[co] = fmaf(v.y, wk, acc1[co]);
                    }
                }
            }
            float m0 = 0.0f, m1 = 0.0f;
#pragma unroll
            for (int co = 0; co < 8; co++) {
                float mw = Wc[OMIX + i * 8 + co];
                m0 = fmaf(fmaxf(acc0[co], 0.0f), mw, m0);
                m1 = fmaf(fmaxf(acc1[co], 0.0f), mw, m1);
            }
            oacc[l - (LBUF - FRAME)]     += m0;
            oacc[l - (LBUF - FRAME) + 1] += m1;
        }
        __syncthreads();
        if (tid < FRAME) out[b * FRAME + tid] = oacc[tid];
    }
}

static const int SMEM_BYTES = (17 * LBUF + FRAME) * (int)sizeof(float) + 8;

extern "C" void kernel_launch(void* const* d_in, const int* in_sizes, int n_in,
                              void* d_out, int out_size) {
    (void)in_sizes; (void)n_in; (void)out_size;
    cudaFuncSetAttribute(wavenet_kernel, cudaFuncAttributeMaxDynamicSharedMemorySize, SMEM_BYTES);

    pack_weights<<<(NW + 511) / 512, 512>>>(
        (const float*)d_in[1], (const float*)d_in[2], (const float*)d_in[3],
        (const float*)d_in[4], (const float*)d_in[5], (const float*)d_in[6],
        (const float*)d_in[7]);

    void* wp = nullptr;
    cudaGetSymbolAddress(&wp, Wstage);
    cudaMemcpyToSymbolAsync(Wc, wp, NW * sizeof(float), 0, cudaMemcpyDeviceToDevice, 0);

    wavenet_kernel<<<128, NTH, SMEM_BYTES>>>((const float*)d_in[0], (float*)d_out);
}